// round 2
// baseline (speedup 1.0000x reference)
#include <cuda_runtime.h>

#define NEDGES 2000000
#define TPB 256
#define EPT 8
#define EDGES_PER_BLOCK (TPB * EPT)

// shared-memory layout (float offsets)
#define OFF_W1   0        // fused [128][128]: cols 0-63 = ew1, 64-127 = ww1
#define OFF_B1   16384    // fused [128]
#define OFF_W2E  16512    // [64][64]
#define OFF_W2W  20608
#define OFF_B2E  24704
#define OFF_B2W  24768
#define OFF_W3E  24832    // [64][32]
#define OFF_W3W  26880
#define OFF_B3E  28928
#define OFF_B3W  28960
#define OFF_W4E  28992    // [32]
#define OFF_W4W  29024
#define OFF_B4   29056    // [0]=e, [1]=w
#define OFF_ACT  29120    // [64][TPB] per-thread activation staging
#define SMEM_FLOATS (OFF_ACT + 64 * TPB)
#define SMEM_BYTES  (SMEM_FLOATS * 4)

__device__ __forceinline__ float lrelu(float z) {
    return fmaxf(z, 0.01f * z);
}

// Layers 2-4 of one MLP branch. Input activations (post-lrelu h1) already in
// stg[k*TPB + tid]. Weight reads are warp-uniform (broadcast). Overwrites stg.
__device__ __forceinline__ float mlp_tail(const float* __restrict__ sm,
                                          float* __restrict__ stg, int tid,
                                          int oW2, int oB2, int oW3, int oB3,
                                          int oW4, float b4v) {
    float h2[64];
    {
        const float4* bp = (const float4*)(sm + oB2);
#pragma unroll
        for (int j4 = 0; j4 < 16; j4++) {
            float4 b = bp[j4];
            h2[4 * j4 + 0] = b.x; h2[4 * j4 + 1] = b.y;
            h2[4 * j4 + 2] = b.z; h2[4 * j4 + 3] = b.w;
        }
    }
#pragma unroll 1
    for (int k = 0; k < 64; k++) {
        float a = stg[k * TPB + tid];
        const float4* wr = (const float4*)(sm + oW2 + k * 64);
#pragma unroll
        for (int j4 = 0; j4 < 16; j4++) {
            float4 w = wr[j4];
            h2[4 * j4 + 0] = fmaf(a, w.x, h2[4 * j4 + 0]);
            h2[4 * j4 + 1] = fmaf(a, w.y, h2[4 * j4 + 1]);
            h2[4 * j4 + 2] = fmaf(a, w.z, h2[4 * j4 + 2]);
            h2[4 * j4 + 3] = fmaf(a, w.w, h2[4 * j4 + 3]);
        }
    }
    // stage lrelu(h2)
#pragma unroll
    for (int j = 0; j < 64; j++) stg[j * TPB + tid] = lrelu(h2[j]);

    float h3[32];
    {
        const float4* bp = (const float4*)(sm + oB3);
#pragma unroll
        for (int j4 = 0; j4 < 8; j4++) {
            float4 b = bp[j4];
            h3[4 * j4 + 0] = b.x; h3[4 * j4 + 1] = b.y;
            h3[4 * j4 + 2] = b.z; h3[4 * j4 + 3] = b.w;
        }
    }
#pragma unroll 1
    for (int k = 0; k < 64; k++) {
        float a = stg[k * TPB + tid];
        const float4* wr = (const float4*)(sm + oW3 + k * 32);
#pragma unroll
        for (int j4 = 0; j4 < 8; j4++) {
            float4 w = wr[j4];
            h3[4 * j4 + 0] = fmaf(a, w.x, h3[4 * j4 + 0]);
            h3[4 * j4 + 1] = fmaf(a, w.y, h3[4 * j4 + 1]);
            h3[4 * j4 + 2] = fmaf(a, w.z, h3[4 * j4 + 2]);
            h3[4 * j4 + 3] = fmaf(a, w.w, h3[4 * j4 + 3]);
        }
    }
    float acc = b4v;
#pragma unroll
    for (int k = 0; k < 32; k++)
        acc = fmaf(lrelu(h3[k]), sm[oW4 + k], acc);
    return acc;
}

__global__ void __launch_bounds__(TPB, 1)
regressor_hybrid_kernel(const float* __restrict__ x_src,
                        const float* __restrict__ x_dst,
                        const int* __restrict__ eidx,
                        const float* __restrict__ ew1, const float* __restrict__ eb1,
                        const float* __restrict__ ww1, const float* __restrict__ wb1,
                        const float* __restrict__ ew2, const float* __restrict__ eb2,
                        const float* __restrict__ ww2, const float* __restrict__ wb2,
                        const float* __restrict__ ew3, const float* __restrict__ eb3,
                        const float* __restrict__ ww3, const float* __restrict__ wb3,
                        const float* __restrict__ ew4, const float* __restrict__ eb4,
                        const float* __restrict__ ww4, const float* __restrict__ wb4,
                        float* __restrict__ out) {
    extern __shared__ float sm[];
    const int tid = threadIdx.x;

    // ---- stage all weights in shared memory ----
    for (int i = tid; i < 128 * 128; i += TPB) {
        int k = i >> 7, j = i & 127;
        sm[OFF_W1 + i] = (j < 64) ? ew1[k * 64 + j] : ww1[k * 64 + (j - 64)];
    }
    for (int i = tid; i < 128; i += TPB)
        sm[OFF_B1 + i] = (i < 64) ? eb1[i] : wb1[i - 64];
    for (int i = tid; i < 64 * 64; i += TPB) {
        sm[OFF_W2E + i] = ew2[i];
        sm[OFF_W2W + i] = ww2[i];
    }
    for (int i = tid; i < 64; i += TPB) {
        sm[OFF_B2E + i] = eb2[i];
        sm[OFF_B2W + i] = wb2[i];
    }
    for (int i = tid; i < 64 * 32; i += TPB) {
        sm[OFF_W3E + i] = ew3[i];
        sm[OFF_W3W + i] = ww3[i];
    }
    if (tid < 32) {
        sm[OFF_B3E + tid] = eb3[tid];
        sm[OFF_B3W + tid] = wb3[tid];
        sm[OFF_W4E + tid] = ew4[tid];
        sm[OFF_W4W + tid] = ww4[tid];
    }
    if (tid == 0) {
        sm[OFF_B4 + 0] = eb4[0];
        sm[OFF_B4 + 1] = wb4[0];
    }
    __syncthreads();

    float* stg = sm + OFF_ACT;

#pragma unroll 1
    for (int it = 0; it < EPT; it++) {
        int e = blockIdx.x * EDGES_PER_BLOCK + it * TPB + tid;
        if (e >= NEDGES) continue;

        int s = eidx[e];
        int d = eidx[NEDGES + e];
        const float4* sp = (const float4*)(x_src + (long long)s * 64);
        const float4* dp = (const float4*)(x_dst + (long long)d * 64);

        // ---- fused layer 1: [128] -> [128] (e-half | w-half) ----
        float h[128];
        {
            const float4* bp = (const float4*)(sm + OFF_B1);
#pragma unroll
            for (int j4 = 0; j4 < 32; j4++) {
                float4 b = bp[j4];
                h[4 * j4 + 0] = b.x; h[4 * j4 + 1] = b.y;
                h[4 * j4 + 2] = b.z; h[4 * j4 + 3] = b.w;
            }
        }
        // src half (k = 0..63)
#pragma unroll 1
        for (int k4 = 0; k4 < 16; k4++) {
            float4 v = sp[k4];
#pragma unroll
            for (int c = 0; c < 4; c++) {
                float a = (c == 0) ? v.x : (c == 1) ? v.y : (c == 2) ? v.z : v.w;
                const float4* wr = (const float4*)(sm + OFF_W1 + (k4 * 4 + c) * 128);
#pragma unroll
                for (int j4 = 0; j4 < 32; j4++) {
                    float4 w = wr[j4];
                    h[4 * j4 + 0] = fmaf(a, w.x, h[4 * j4 + 0]);
                    h[4 * j4 + 1] = fmaf(a, w.y, h[4 * j4 + 1]);
                    h[4 * j4 + 2] = fmaf(a, w.z, h[4 * j4 + 2]);
                    h[4 * j4 + 3] = fmaf(a, w.w, h[4 * j4 + 3]);
                }
            }
        }
        // dst half (k = 64..127)
#pragma unroll 1
        for (int k4 = 0; k4 < 16; k4++) {
            float4 v = dp[k4];
#pragma unroll
            for (int c = 0; c < 4; c++) {
                float a = (c == 0) ? v.x : (c == 1) ? v.y : (c == 2) ? v.z : v.w;
                const float4* wr = (const float4*)(sm + OFF_W1 + (64 + k4 * 4 + c) * 128);
#pragma unroll
                for (int j4 = 0; j4 < 32; j4++) {
                    float4 w = wr[j4];
                    h[4 * j4 + 0] = fmaf(a, w.x, h[4 * j4 + 0]);
                    h[4 * j4 + 1] = fmaf(a, w.y, h[4 * j4 + 1]);
                    h[4 * j4 + 2] = fmaf(a, w.z, h[4 * j4 + 2]);
                    h[4 * j4 + 3] = fmaf(a, w.w, h[4 * j4 + 3]);
                }
            }
        }

        // ---- e-branch (link_exists): stage lrelu(h[0..63]) then tail ----
#pragma unroll
        for (int j = 0; j < 64; j++) stg[j * TPB + tid] = lrelu(h[j]);
        float oe = mlp_tail(sm, stg, tid, OFF_W2E, OFF_B2E, OFF_W3E, OFF_B3E,
                            OFF_W4E, sm[OFF_B4 + 0]);

        // ---- w-branch (link_weight): stage lrelu(h[64..127]) then tail ----
#pragma unroll
        for (int j = 0; j < 64; j++) stg[j * TPB + tid] = lrelu(h[64 + j]);
        float ow = mlp_tail(sm, stg, tid, OFF_W2W, OFF_B2W, OFF_W3W, OFF_B3W,
                            OFF_W4W, sm[OFF_B4 + 1]);

        out[e] = oe;
        out[NEDGES + e] = ow;
    }
}

extern "C" void kernel_launch(void* const* d_in, const int* in_sizes, int n_in,
                              void* d_out, int out_size) {
    const float* x_src = (const float*)d_in[0];
    const float* x_dst = (const float*)d_in[1];
    const int* eidx = (const int*)d_in[2];
    const float* ew1 = (const float*)d_in[3];
    const float* eb1 = (const float*)d_in[4];
    const float* ww1 = (const float*)d_in[5];
    const float* wb1 = (const float*)d_in[6];
    const float* ew2 = (const float*)d_in[7];
    const float* eb2 = (const float*)d_in[8];
    const float* ww2 = (const float*)d_in[9];
    const float* wb2 = (const float*)d_in[10];
    const float* ew3 = (const float*)d_in[11];
    const float* eb3 = (const float*)d_in[12];
    const float* ww3 = (const float*)d_in[13];
    const float* wb3 = (const float*)d_in[14];
    const float* ew4 = (const float*)d_in[15];
    const float* eb4 = (const float*)d_in[16];
    const float* ww4 = (const float*)d_in[17];
    const float* wb4 = (const float*)d_in[18];
    float* out = (float*)d_out;

    cudaFuncSetAttribute(regressor_hybrid_kernel,
                         cudaFuncAttributeMaxDynamicSharedMemorySize, SMEM_BYTES);

    int blocks = (NEDGES + EDGES_PER_BLOCK - 1) / EDGES_PER_BLOCK;
    regressor_hybrid_kernel<<<blocks, TPB, SMEM_BYTES>>>(
        x_src, x_dst, eidx, ew1, eb1, ww1, wb1, ew2, eb2, ww2, wb2,
        ew3, eb3, ww3, wb3, ew4, eb4, ww4, wb4, out);
}

// round 4
// speedup vs baseline: 3.0649x; 3.0649x over previous
#include <cuda_runtime.h>
#include <cuda_bf16.h>
#include <cstdint>

#define NEDGES 2000000
#define TILE_M 128
#define NTILES (NEDGES / TILE_M)
#define TPB 256

// activation buffers: [128 rows][136 bf16] (272 B stride, conflict-free ldmatrix)
#define ROWB 272
#define SM_XH 0
#define SM_XL 34816
#define SM_YH 69632
#define SM_YL 104448
#define SM_P  139264            // float[2][128][4]
#define SM_B4 143360            // float[2]
#define SMEM_BYTES 143424

__device__ __forceinline__ uint32_t smem_u32(const void* p) {
    uint32_t a;
    asm("{ .reg .u64 t; cvta.to.shared.u64 t, %1; cvt.u32.u64 %0, t; }" : "=r"(a) : "l"(p));
    return a;
}
__device__ __forceinline__ float lrelu(float z) { return fmaxf(z, 0.01f * z); }

// pack 2 f32 -> bf16x2 (a in low half)
__device__ __forceinline__ uint32_t pk2(float a, float b) {
    uint32_t r;
    asm("cvt.rn.bf16x2.f32 %0, %1, %2;" : "=r"(r) : "f"(b), "f"(a));
    return r;
}
// split f32 pair -> hi bf16x2 + lo bf16x2
__device__ __forceinline__ void split2(float a, float b, uint32_t& hp, uint32_t& lp) {
    hp = pk2(a, b);
    float ha = __uint_as_float(hp << 16);
    float hb = __uint_as_float(hp & 0xFFFF0000u);
    lp = pk2(a - ha, b - hb);
}

__device__ __forceinline__ void ldsm4(uint32_t addr, uint32_t& a0, uint32_t& a1,
                                      uint32_t& a2, uint32_t& a3) {
    asm volatile("ldmatrix.sync.aligned.m8n8.x4.shared.b16 {%0,%1,%2,%3}, [%4];"
                 : "=r"(a0), "=r"(a1), "=r"(a2), "=r"(a3) : "r"(addr));
}
__device__ __forceinline__ void mma16816(float* d, uint32_t a0, uint32_t a1,
                                         uint32_t a2, uint32_t a3,
                                         uint32_t b0, uint32_t b1) {
    asm volatile(
        "mma.sync.aligned.m16n8k16.row.col.f32.bf16.bf16.f32 "
        "{%0,%1,%2,%3}, {%4,%5,%6,%7}, {%8,%9}, {%0,%1,%2,%3};"
        : "+f"(d[0]), "+f"(d[1]), "+f"(d[2]), "+f"(d[3])
        : "r"(a0), "r"(a1), "r"(a2), "r"(a3), "r"(b0), "r"(b1));
}

// build one 8x8 B fragment (col-major k8 x n8) from global W[k][n] (row-major, ldn)
__device__ __forceinline__ void make_bfrag(const float* __restrict__ W, int ldn,
                                           int k0, int n0, int lane,
                                           uint32_t& h, uint32_t& l) {
    int g = lane >> 2, tg = lane & 3;
    const float* p = W + (size_t)(k0 + tg * 2) * ldn + (n0 + g);
    float wa = p[0], wb = p[ldn];
    h = pk2(wa, wb);
    float ha = __uint_as_float(h << 16);
    float hb = __uint_as_float(h & 0xFFFF0000u);
    l = pk2(wa - ha, wb - hb);
}

__global__ void __launch_bounds__(TPB, 1)
regressor_mma_kernel(const float* __restrict__ x_src,
                     const float* __restrict__ x_dst,
                     const int* __restrict__ eidx,
                     const float* __restrict__ ew1, const float* __restrict__ eb1,
                     const float* __restrict__ ww1, const float* __restrict__ wb1,
                     const float* __restrict__ ew2, const float* __restrict__ eb2,
                     const float* __restrict__ ww2, const float* __restrict__ wb2,
                     const float* __restrict__ ew3, const float* __restrict__ eb3,
                     const float* __restrict__ ww3, const float* __restrict__ wb3,
                     const float* __restrict__ ew4, const float* __restrict__ eb4,
                     const float* __restrict__ ww4, const float* __restrict__ wb4,
                     float* __restrict__ out) {
    extern __shared__ char smem[];
    const uint32_t smb = smem_u32(smem);
    const int tid = threadIdx.x;
    const int wid = tid >> 5, lane = tid & 31;
    const int branch = wid >> 2;           // 0 = exists, 1 = weight
    const int nloc = (wid & 3) * 16;       // warp's n-slice within the branch (L1/L2)
    const int n3 = (wid & 3) * 8;          // warp's n-slice for L3

    // ---------- per-warp weight fragments (registers, built once) ----------
    const float* W1 = branch ? ww1 : ew1;  // [128][64]
    const float* W2 = branch ? ww2 : ew2;  // [64][64]
    const float* W3 = branch ? ww3 : ew3;  // [64][32]
    const float* B1 = branch ? wb1 : eb1;
    const float* B2 = branch ? wb2 : eb2;
    const float* B3 = branch ? wb3 : eb3;
    const float* W4 = branch ? ww4 : ew4;

    uint32_t B1h[8][2][2], B1l[8][2][2];
#pragma unroll
    for (int kt = 0; kt < 8; kt++)
#pragma unroll
        for (int nt = 0; nt < 2; nt++)
#pragma unroll
            for (int r = 0; r < 2; r++)
                make_bfrag(W1, 64, kt * 16 + r * 8, nloc + nt * 8, lane,
                           B1h[kt][nt][r], B1l[kt][nt][r]);

    uint32_t B2h[4][2][2], B2l[4][2][2];
#pragma unroll
    for (int kt = 0; kt < 4; kt++)
#pragma unroll
        for (int nt = 0; nt < 2; nt++)
#pragma unroll
            for (int r = 0; r < 2; r++)
                make_bfrag(W2, 64, kt * 16 + r * 8, nloc + nt * 8, lane,
                           B2h[kt][nt][r], B2l[kt][nt][r]);

    uint32_t B3h[4][2], B3l[4][2];
#pragma unroll
    for (int kt = 0; kt < 4; kt++)
#pragma unroll
        for (int r = 0; r < 2; r++)
            make_bfrag(W3, 32, kt * 16 + r * 8, n3, lane, B3h[kt][r], B3l[kt][r]);

    // per-thread biases for the columns this thread's c-frag covers
    float b1v[2][2], b2v[2][2], b3v[2], w4v[2];
#pragma unroll
    for (int nt = 0; nt < 2; nt++)
#pragma unroll
        for (int j = 0; j < 2; j++) {
            int c = nloc + nt * 8 + (lane & 3) * 2 + j;
            b1v[nt][j] = B1[c];
            b2v[nt][j] = B2[c];
        }
#pragma unroll
    for (int j = 0; j < 2; j++) {
        int c = n3 + (lane & 3) * 2 + j;
        b3v[j] = B3[c];
        w4v[j] = W4[c];
    }
    if (tid == 0) {
        *(float*)(smem + SM_B4 + 0) = eb4[0];
        *(float*)(smem + SM_B4 + 4) = wb4[0];
    }
    __syncthreads();

    const uint32_t xh = smb + SM_XH, xl = smb + SM_XL;
    const uint32_t yh = smb + SM_YH, yl = smb + SM_YL;

    for (int t = blockIdx.x; t < NTILES; t += gridDim.x) {
        // ===== gather: warp w owns edges [16w,16w+16); lanes 0-15 src, 16-31 dst =====
        {
            const int half = lane >> 4;
            const int c16 = lane & 15;
#pragma unroll 1
            for (int i = 0; i < 16; i++) {
                int m = wid * 16 + i;
                int e = t * TILE_M + m;
                int idx = half ? eidx[NEDGES + e] : eidx[e];
                const float* row = (half ? x_dst : x_src) + (size_t)idx * 64;
                float4 v = ((const float4*)row)[c16];
                uint32_t h0, l0, h1, l1;
                split2(v.x, v.y, h0, l0);
                split2(v.z, v.w, h1, l1);
                uint32_t off = (uint32_t)m * ROWB + half * 128u + c16 * 8u;
                *(uint2*)(smem + SM_XH + off) = make_uint2(h0, h1);
                *(uint2*)(smem + SM_XL + off) = make_uint2(l0, l1);
            }
        }
        __syncthreads();

        // ===== L1: X[128x128] -> Y[128x128] =====
        {
            const int colout = branch * 64 + nloc;
#pragma unroll 1
            for (int mt = 0; mt < 8; mt++) {
                int m0 = mt * 16;
                float aP[2][4] = {{0, 0, 0, 0}, {0, 0, 0, 0}};
                float aQ[2][4] = {{0, 0, 0, 0}, {0, 0, 0, 0}};
                uint32_t arow = (uint32_t)(m0 + (lane & 15)) * ROWB + (lane >> 4) * 16u;
#pragma unroll
                for (int kt = 0; kt < 8; kt++) {
                    uint32_t h0, h1, h2, h3, l0, l1, l2, l3;
                    ldsm4(xh + arow + kt * 32u, h0, h1, h2, h3);
                    ldsm4(xl + arow + kt * 32u, l0, l1, l2, l3);
#pragma unroll
                    for (int nt = 0; nt < 2; nt++) {
                        mma16816(aP[nt], h0, h1, h2, h3, B1h[kt][nt][0], B1h[kt][nt][1]);
                        mma16816(aQ[nt], h0, h1, h2, h3, B1l[kt][nt][0], B1l[kt][nt][1]);
                        mma16816(aQ[nt], l0, l1, l2, l3, B1h[kt][nt][0], B1h[kt][nt][1]);
                    }
                }
#pragma unroll
                for (int nt = 0; nt < 2; nt++) {
                    float v0 = lrelu(aP[nt][0] + aQ[nt][0] + b1v[nt][0]);
                    float v1 = lrelu(aP[nt][1] + aQ[nt][1] + b1v[nt][1]);
                    float v2 = lrelu(aP[nt][2] + aQ[nt][2] + b1v[nt][0]);
                    float v3 = lrelu(aP[nt][3] + aQ[nt][3] + b1v[nt][1]);
                    uint32_t hp0, lp0, hp1, lp1;
                    split2(v0, v1, hp0, lp0);
                    split2(v2, v3, hp1, lp1);
                    uint32_t col2 = (uint32_t)(colout + nt * 8 + (lane & 3) * 2) * 2u;
                    uint32_t o0 = (uint32_t)(m0 + (lane >> 2)) * ROWB + col2;
                    uint32_t o1 = (uint32_t)(m0 + 8 + (lane >> 2)) * ROWB + col2;
                    *(uint32_t*)(smem + SM_YH + o0) = hp0;
                    *(uint32_t*)(smem + SM_YL + o0) = lp0;
                    *(uint32_t*)(smem + SM_YH + o1) = hp1;
                    *(uint32_t*)(smem + SM_YL + o1) = lp1;
                }
            }
        }
        __syncthreads();

        // ===== L2: Y (cols branch*64..+63) -> X =====
        {
            const int colout = branch * 64 + nloc;
            const uint32_t abase = (uint32_t)branch * 128u;
#pragma unroll 1
            for (int mt = 0; mt < 8; mt++) {
                int m0 = mt * 16;
                float aP[2][4] = {{0, 0, 0, 0}, {0, 0, 0, 0}};
                float aQ[2][4] = {{0, 0, 0, 0}, {0, 0, 0, 0}};
                uint32_t arow = (uint32_t)(m0 + (lane & 15)) * ROWB + abase + (lane >> 4) * 16u;
#pragma unroll
                for (int kt = 0; kt < 4; kt++) {
                    uint32_t h0, h1, h2, h3, l0, l1, l2, l3;
                    ldsm4(yh + arow + kt * 32u, h0, h1, h2, h3);
                    ldsm4(yl + arow + kt * 32u, l0, l1, l2, l3);
#pragma unroll
                    for (int nt = 0; nt < 2; nt++) {
                        mma16816(aP[nt], h0, h1, h2, h3, B2h[kt][nt][0], B2h[kt][nt][1]);
                        mma16816(aQ[nt], h0, h1, h2, h3, B2l[kt][nt][0], B2l[kt][nt][1]);
                        mma16816(aQ[nt], l0, l1, l2, l3, B2h[kt][nt][0], B2h[kt][nt][1]);
                    }
                }
#pragma unroll
                for (int nt = 0; nt < 2; nt++) {
                    float v0 = lrelu(aP[nt][0] + aQ[nt][0] + b2v[nt][0]);
                    float v1 = lrelu(aP[nt][1] + aQ[nt][1] + b2v[nt][1]);
                    float v2 = lrelu(aP[nt][2] + aQ[nt][2] + b2v[nt][0]);
                    float v3 = lrelu(aP[nt][3] + aQ[nt][3] + b2v[nt][1]);
                    uint32_t hp0, lp0, hp1, lp1;
                    split2(v0, v1, hp0, lp0);
                    split2(v2, v3, hp1, lp1);
                    uint32_t col2 = (uint32_t)(colout + nt * 8 + (lane & 3) * 2) * 2u;
                    uint32_t o0 = (uint32_t)(m0 + (lane >> 2)) * ROWB + col2;
                    uint32_t o1 = (uint32_t)(m0 + 8 + (lane >> 2)) * ROWB + col2;
                    *(uint32_t*)(smem + SM_XH + o0) = hp0;
                    *(uint32_t*)(smem + SM_XL + o0) = lp0;
                    *(uint32_t*)(smem + SM_XH + o1) = hp1;
                    *(uint32_t*)(smem + SM_XL + o1) = lp1;
                }
            }
        }
        __syncthreads();

        // ===== L3 + L4: X (cols branch*64..) -> partials in P =====
        {
            const uint32_t abase = (uint32_t)branch * 128u;
            float* P = (float*)(smem + SM_P);
#pragma unroll 1
            for (int mt = 0; mt < 8; mt++) {
                int m0 = mt * 16;
                float aP[4] = {0, 0, 0, 0};
                float aQ[4] = {0, 0, 0, 0};
                uint32_t arow = (uint32_t)(m0 + (lane & 15)) * ROWB + abase + (lane >> 4) * 16u;
#pragma unroll
                for (int kt = 0; kt < 4; kt++) {
                    uint32_t h0, h1, h2, h3, l0, l1, l2, l3;
                    ldsm4(xh + arow + kt * 32u, h0, h1, h2, h3);
                    ldsm4(xl + arow + kt * 32u, l0, l1, l2, l3);
                    mma16816(aP, h0, h1, h2, h3, B3h[kt][0], B3h[kt][1]);
                    mma16816(aQ, h0, h1, h2, h3, B3l[kt][0], B3l[kt][1]);
                    mma16816(aQ, l0, l1, l2, l3, B3h[kt][0], B3h[kt][1]);
                }
                float p0 = lrelu(aP[0] + aQ[0] + b3v[0]) * w4v[0] +
                           lrelu(aP[1] + aQ[1] + b3v[1]) * w4v[1];
                float p1 = lrelu(aP[2] + aQ[2] + b3v[0]) * w4v[0] +
                           lrelu(aP[3] + aQ[3] + b3v[1]) * w4v[1];
                p0 += __shfl_xor_sync(0xFFFFFFFFu, p0, 1);
                p0 += __shfl_xor_sync(0xFFFFFFFFu, p0, 2);
                p1 += __shfl_xor_sync(0xFFFFFFFFu, p1, 1);
                p1 += __shfl_xor_sync(0xFFFFFFFFu, p1, 2);
                if ((lane & 3) == 0) {
                    int r0 = m0 + (lane >> 2);
                    P[((branch << 7) + r0) * 4 + (wid & 3)] = p0;
                    P[((branch << 7) + r0 + 8) * 4 + (wid & 3)] = p1;
                }
            }
        }
        __syncthreads();

        // ===== final reduce + store =====
        {
            int br = tid >> 7, m = tid & 127;
            float4 pv = *(const float4*)(smem + SM_P + ((br << 7) + m) * 16);
            float b4 = *(const float*)(smem + SM_B4 + br * 4);
            out[br * NEDGES + t * TILE_M + m] = pv.x + pv.y + pv.z + pv.w + b4;
        }
        // no hazard: next phase that writes P is 3 syncs away; gather writes X,
        // whose last readers (L3 ldmatrix) completed before the sync above.
    }
}

extern "C" void kernel_launch(void* const* d_in, const int* in_sizes, int n_in,
                              void* d_out, int out_size) {
    const float* x_src = (const float*)d_in[0];
    const float* x_dst = (const float*)d_in[1];
    const int* eidx = (const int*)d_in[2];
    const float* ew1 = (const float*)d_in[3];
    const float* eb1 = (const float*)d_in[4];
    const float* ww1 = (const float*)d_in[5];
    const float* wb1 = (const float*)d_in[6];
    const float* ew2 = (const float*)d_in[7];
    const float* eb2 = (const float*)d_in[8];
    const float* ww2 = (const float*)d_in[9];
    const float* wb2 = (const float*)d_in[10];
    const float* ew3 = (const float*)d_in[11];
    const float* eb3 = (const float*)d_in[12];
    const float* ww3 = (const float*)d_in[13];
    const float* wb3 = (const float*)d_in[14];
    const float* ew4 = (const float*)d_in[15];
    const float* eb4 = (const float*)d_in[16];
    const float* ww4 = (const float*)d_in[17];
    const float* wb4 = (const float*)d_in[18];
    float* out = (float*)d_out;

    int nsm = 148;
    cudaDeviceGetAttribute(&nsm, cudaDevAttrMultiProcessorCount, 0);

    cudaFuncSetAttribute(regressor_mma_kernel,
                         cudaFuncAttributeMaxDynamicSharedMemorySize, SMEM_BYTES);

    regressor_mma_kernel<<<nsm, TPB, SMEM_BYTES>>>(
        x_src, x_dst, eidx, ew1, eb1, ww1, wb1, ew2, eb2, ww2, wb2,
        ew3, eb3, ww3, wb3, ew4, eb4, ww4, wb4, out);
}

// round 5
// speedup vs baseline: 3.3890x; 1.1057x over previous
#include <cuda_runtime.h>
#include <cuda_bf16.h>
#include <cstdint>

#define NEDGES 2000000
#define TILE_M 128
#define NTILES (NEDGES / TILE_M)
#define TPB 256

// activation buffers: [128 rows][136 bf16] (272 B stride, conflict-free ldmatrix)
#define ROWB 272
#define SM_XH 0
#define SM_XL 34816
#define SM_YH 69632
#define SM_YL 104448
#define SM_P  139264            // float[2][128][4]
#define SM_B4 143360            // float[2]
#define SMEM_BYTES 143424

__device__ __forceinline__ uint32_t smem_u32(const void* p) {
    uint32_t a;
    asm("{ .reg .u64 t; cvta.to.shared.u64 t, %1; cvt.u32.u64 %0, t; }" : "=r"(a) : "l"(p));
    return a;
}
__device__ __forceinline__ float lrelu(float z) { return fmaxf(z, 0.01f * z); }

// pack 2 f32 -> bf16x2 (a in low half)
__device__ __forceinline__ uint32_t pk2(float a, float b) {
    uint32_t r;
    asm("cvt.rn.bf16x2.f32 %0, %1, %2;" : "=r"(r) : "f"(b), "f"(a));
    return r;
}
// split f32 pair -> hi bf16x2 + lo bf16x2
__device__ __forceinline__ void split2(float a, float b, uint32_t& hp, uint32_t& lp) {
    hp = pk2(a, b);
    float ha = __uint_as_float(hp << 16);
    float hb = __uint_as_float(hp & 0xFFFF0000u);
    lp = pk2(a - ha, b - hb);
}

__device__ __forceinline__ void ldsm4(uint32_t addr, uint32_t& a0, uint32_t& a1,
                                      uint32_t& a2, uint32_t& a3) {
    asm volatile("ldmatrix.sync.aligned.m8n8.x4.shared.b16 {%0,%1,%2,%3}, [%4];"
                 : "=r"(a0), "=r"(a1), "=r"(a2), "=r"(a3) : "r"(addr));
}
__device__ __forceinline__ void mma16816(float* d, uint32_t a0, uint32_t a1,
                                         uint32_t a2, uint32_t a3,
                                         uint32_t b0, uint32_t b1) {
    asm volatile(
        "mma.sync.aligned.m16n8k16.row.col.f32.bf16.bf16.f32 "
        "{%0,%1,%2,%3}, {%4,%5,%6,%7}, {%8,%9}, {%0,%1,%2,%3};"
        : "+f"(d[0]), "+f"(d[1]), "+f"(d[2]), "+f"(d[3])
        : "r"(a0), "r"(a1), "r"(a2), "r"(a3), "r"(b0), "r"(b1));
}

// build one 8x8 B fragment (col-major k8 x n8) from global W[k][n] (row-major, ldn)
__device__ __forceinline__ void make_bfrag(const float* __restrict__ W, int ldn,
                                           int k0, int n0, int lane,
                                           uint32_t& h, uint32_t& l) {
    int g = lane >> 2, tg = lane & 3;
    const float* p = W + (size_t)(k0 + tg * 2) * ldn + (n0 + g);
    float wa = p[0], wb = p[ldn];
    h = pk2(wa, wb);
    float ha = __uint_as_float(h << 16);
    float hb = __uint_as_float(h & 0xFFFF0000u);
    l = pk2(wa - ha, wb - hb);
}

__global__ void __launch_bounds__(TPB, 1)
regressor_mma_kernel(const float* __restrict__ x_src,
                     const float* __restrict__ x_dst,
                     const int* __restrict__ eidx,
                     const float* __restrict__ ew1, const float* __restrict__ eb1,
                     const float* __restrict__ ww1, const float* __restrict__ wb1,
                     const float* __restrict__ ew2, const float* __restrict__ eb2,
                     const float* __restrict__ ww2, const float* __restrict__ wb2,
                     const float* __restrict__ ew3, const float* __restrict__ eb3,
                     const float* __restrict__ ww3, const float* __restrict__ wb3,
                     const float* __restrict__ ew4, const float* __restrict__ eb4,
                     const float* __restrict__ ww4, const float* __restrict__ wb4,
                     float* __restrict__ out) {
    extern __shared__ char smem[];
    const uint32_t smb = smem_u32(smem);
    const int tid = threadIdx.x;
    const int wid = tid >> 5, lane = tid & 31;
    const int branch = wid >> 2;           // 0 = exists, 1 = weight
    const int nloc = (wid & 3) * 16;       // warp's n-slice within the branch (L1/L2)
    const int n3 = (wid & 3) * 8;          // warp's n-slice for L3

    // ---------- per-warp weight fragments (registers, built once) ----------
    const float* W1 = branch ? ww1 : ew1;  // [128][64]
    const float* W2 = branch ? ww2 : ew2;  // [64][64]
    const float* W3 = branch ? ww3 : ew3;  // [64][32]
    const float* B1 = branch ? wb1 : eb1;
    const float* B2 = branch ? wb2 : eb2;
    const float* B3 = branch ? wb3 : eb3;
    const float* W4 = branch ? ww4 : ew4;

    uint32_t B1h[8][2][2], B1l[8][2][2];
#pragma unroll
    for (int kt = 0; kt < 8; kt++)
#pragma unroll
        for (int nt = 0; nt < 2; nt++)
#pragma unroll
            for (int r = 0; r < 2; r++)
                make_bfrag(W1, 64, kt * 16 + r * 8, nloc + nt * 8, lane,
                           B1h[kt][nt][r], B1l[kt][nt][r]);

    uint32_t B2h[4][2][2], B2l[4][2][2];
#pragma unroll
    for (int kt = 0; kt < 4; kt++)
#pragma unroll
        for (int nt = 0; nt < 2; nt++)
#pragma unroll
            for (int r = 0; r < 2; r++)
                make_bfrag(W2, 64, kt * 16 + r * 8, nloc + nt * 8, lane,
                           B2h[kt][nt][r], B2l[kt][nt][r]);

    uint32_t B3h[4][2], B3l[4][2];
#pragma unroll
    for (int kt = 0; kt < 4; kt++)
#pragma unroll
        for (int r = 0; r < 2; r++)
            make_bfrag(W3, 32, kt * 16 + r * 8, n3, lane, B3h[kt][r], B3l[kt][r]);

    // per-thread biases for the columns this thread's c-frag covers
    float b1v[2][2], b2v[2][2], b3v[2], w4v[2];
#pragma unroll
    for (int nt = 0; nt < 2; nt++)
#pragma unroll
        for (int j = 0; j < 2; j++) {
            int c = nloc + nt * 8 + (lane & 3) * 2 + j;
            b1v[nt][j] = B1[c];
            b2v[nt][j] = B2[c];
        }
#pragma unroll
    for (int j = 0; j < 2; j++) {
        int c = n3 + (lane & 3) * 2 + j;
        b3v[j] = B3[c];
        w4v[j] = W4[c];
    }
    if (tid == 0) {
        *(float*)(smem + SM_B4 + 0) = eb4[0];
        *(float*)(smem + SM_B4 + 4) = wb4[0];
    }
    __syncthreads();

    const uint32_t xh = smb + SM_XH, xl = smb + SM_XL;
    const uint32_t yh = smb + SM_YH, yl = smb + SM_YL;

    for (int t = blockIdx.x; t < NTILES; t += gridDim.x) {
        // ===== gather: warp w owns edges [16w,16w+16); lanes 0-15 src, 16-31 dst =====
        {
            const int half = lane >> 4;
            const int c16 = lane & 15;
#pragma unroll 2
            for (int i = 0; i < 16; i++) {
                int m = wid * 16 + i;
                int e = t * TILE_M + m;
                int idx = half ? eidx[NEDGES + e] : eidx[e];
                const float* row = (half ? x_dst : x_src) + (size_t)idx * 64;
                float4 v = ((const float4*)row)[c16];
                uint32_t h0, l0, h1, l1;
                split2(v.x, v.y, h0, l0);
                split2(v.z, v.w, h1, l1);
                uint32_t off = (uint32_t)m * ROWB + half * 128u + c16 * 8u;
                *(uint2*)(smem + SM_XH + off) = make_uint2(h0, h1);
                *(uint2*)(smem + SM_XL + off) = make_uint2(l0, l1);
            }
        }
        __syncthreads();

        // ===== L1: X[128x128] -> Y[128x128], paired m-tiles, 3-way chains =====
        {
            const int colout = branch * 64 + nloc;
#pragma unroll 1
            for (int mt = 0; mt < 8; mt += 2) {
                float aP[2][2][4] = {};
                float aQ1[2][2][4] = {};
                float aQ2[2][2][4] = {};
                uint32_t arow0 = (uint32_t)(mt * 16 + (lane & 15)) * ROWB + (lane >> 4) * 16u;
                uint32_t arow1 = arow0 + 16u * ROWB;
#pragma unroll
                for (int kt = 0; kt < 8; kt++) {
                    uint32_t h0[2], h1[2], h2[2], h3[2], l0[2], l1[2], l2[2], l3[2];
                    ldsm4(xh + arow0 + kt * 32u, h0[0], h1[0], h2[0], h3[0]);
                    ldsm4(xl + arow0 + kt * 32u, l0[0], l1[0], l2[0], l3[0]);
                    ldsm4(xh + arow1 + kt * 32u, h0[1], h1[1], h2[1], h3[1]);
                    ldsm4(xl + arow1 + kt * 32u, l0[1], l1[1], l2[1], l3[1]);
#pragma unroll
                    for (int u = 0; u < 2; u++)
#pragma unroll
                        for (int nt = 0; nt < 2; nt++) {
                            mma16816(aP[u][nt], h0[u], h1[u], h2[u], h3[u],
                                     B1h[kt][nt][0], B1h[kt][nt][1]);
                            mma16816(aQ1[u][nt], h0[u], h1[u], h2[u], h3[u],
                                     B1l[kt][nt][0], B1l[kt][nt][1]);
                            mma16816(aQ2[u][nt], l0[u], l1[u], l2[u], l3[u],
                                     B1h[kt][nt][0], B1h[kt][nt][1]);
                        }
                }
#pragma unroll
                for (int u = 0; u < 2; u++) {
                    int m0 = (mt + u) * 16;
#pragma unroll
                    for (int nt = 0; nt < 2; nt++) {
                        float v0 = lrelu(aP[u][nt][0] + aQ1[u][nt][0] + aQ2[u][nt][0] + b1v[nt][0]);
                        float v1 = lrelu(aP[u][nt][1] + aQ1[u][nt][1] + aQ2[u][nt][1] + b1v[nt][1]);
                        float v2 = lrelu(aP[u][nt][2] + aQ1[u][nt][2] + aQ2[u][nt][2] + b1v[nt][0]);
                        float v3 = lrelu(aP[u][nt][3] + aQ1[u][nt][3] + aQ2[u][nt][3] + b1v[nt][1]);
                        uint32_t hp0, lp0, hp1, lp1;
                        split2(v0, v1, hp0, lp0);
                        split2(v2, v3, hp1, lp1);
                        uint32_t col2 = (uint32_t)(colout + nt * 8 + (lane & 3) * 2) * 2u;
                        uint32_t o0 = (uint32_t)(m0 + (lane >> 2)) * ROWB + col2;
                        uint32_t o1 = (uint32_t)(m0 + 8 + (lane >> 2)) * ROWB + col2;
                        *(uint32_t*)(smem + SM_YH + o0) = hp0;
                        *(uint32_t*)(smem + SM_YL + o0) = lp0;
                        *(uint32_t*)(smem + SM_YH + o1) = hp1;
                        *(uint32_t*)(smem + SM_YL + o1) = lp1;
                    }
                }
            }
        }
        __syncthreads();

        // ===== L2: Y (cols branch*64..+63) -> X, 3-way chains =====
        {
            const int colout = branch * 64 + nloc;
            const uint32_t abase = (uint32_t)branch * 128u;
#pragma unroll 1
            for (int mt = 0; mt < 8; mt++) {
                int m0 = mt * 16;
                float aP[2][4] = {};
                float aQ1[2][4] = {};
                float aQ2[2][4] = {};
                uint32_t arow = (uint32_t)(m0 + (lane & 15)) * ROWB + abase + (lane >> 4) * 16u;
#pragma unroll
                for (int kt = 0; kt < 4; kt++) {
                    uint32_t h0, h1, h2, h3, l0, l1, l2, l3;
                    ldsm4(yh + arow + kt * 32u, h0, h1, h2, h3);
                    ldsm4(yl + arow + kt * 32u, l0, l1, l2, l3);
#pragma unroll
                    for (int nt = 0; nt < 2; nt++) {
                        mma16816(aP[nt], h0, h1, h2, h3, B2h[kt][nt][0], B2h[kt][nt][1]);
                        mma16816(aQ1[nt], h0, h1, h2, h3, B2l[kt][nt][0], B2l[kt][nt][1]);
                        mma16816(aQ2[nt], l0, l1, l2, l3, B2h[kt][nt][0], B2h[kt][nt][1]);
                    }
                }
#pragma unroll
                for (int nt = 0; nt < 2; nt++) {
                    float v0 = lrelu(aP[nt][0] + aQ1[nt][0] + aQ2[nt][0] + b2v[nt][0]);
                    float v1 = lrelu(aP[nt][1] + aQ1[nt][1] + aQ2[nt][1] + b2v[nt][1]);
                    float v2 = lrelu(aP[nt][2] + aQ1[nt][2] + aQ2[nt][2] + b2v[nt][0]);
                    float v3 = lrelu(aP[nt][3] + aQ1[nt][3] + aQ2[nt][3] + b2v[nt][1]);
                    uint32_t hp0, lp0, hp1, lp1;
                    split2(v0, v1, hp0, lp0);
                    split2(v2, v3, hp1, lp1);
                    uint32_t col2 = (uint32_t)(colout + nt * 8 + (lane & 3) * 2) * 2u;
                    uint32_t o0 = (uint32_t)(m0 + (lane >> 2)) * ROWB + col2;
                    uint32_t o1 = (uint32_t)(m0 + 8 + (lane >> 2)) * ROWB + col2;
                    *(uint32_t*)(smem + SM_XH + o0) = hp0;
                    *(uint32_t*)(smem + SM_XL + o0) = lp0;
                    *(uint32_t*)(smem + SM_XH + o1) = hp1;
                    *(uint32_t*)(smem + SM_XL + o1) = lp1;
                }
            }
        }
        __syncthreads();

        // ===== L3 + L4: X (cols branch*64..) -> partials in P =====
        {
            const uint32_t abase = (uint32_t)branch * 128u;
            float* P = (float*)(smem + SM_P);
#pragma unroll 1
            for (int mt = 0; mt < 8; mt++) {
                int m0 = mt * 16;
                float aP[4] = {0, 0, 0, 0};
                float aQ1[4] = {0, 0, 0, 0};
                float aQ2[4] = {0, 0, 0, 0};
                uint32_t arow = (uint32_t)(m0 + (lane & 15)) * ROWB + abase + (lane >> 4) * 16u;
#pragma unroll
                for (int kt = 0; kt < 4; kt++) {
                    uint32_t h0, h1, h2, h3, l0, l1, l2, l3;
                    ldsm4(xh + arow + kt * 32u, h0, h1, h2, h3);
                    ldsm4(xl + arow + kt * 32u, l0, l1, l2, l3);
                    mma16816(aP, h0, h1, h2, h3, B3h[kt][0], B3h[kt][1]);
                    mma16816(aQ1, h0, h1, h2, h3, B3l[kt][0], B3l[kt][1]);
                    mma16816(aQ2, l0, l1, l2, l3, B3h[kt][0], B3h[kt][1]);
                }
                float p0 = lrelu(aP[0] + aQ1[0] + aQ2[0] + b3v[0]) * w4v[0] +
                           lrelu(aP[1] + aQ1[1] + aQ2[1] + b3v[1]) * w4v[1];
                float p1 = lrelu(aP[2] + aQ1[2] + aQ2[2] + b3v[0]) * w4v[0] +
                           lrelu(aP[3] + aQ1[3] + aQ2[3] + b3v[1]) * w4v[1];
                p0 += __shfl_xor_sync(0xFFFFFFFFu, p0, 1);
                p0 += __shfl_xor_sync(0xFFFFFFFFu, p0, 2);
                p1 += __shfl_xor_sync(0xFFFFFFFFu, p1, 1);
                p1 += __shfl_xor_sync(0xFFFFFFFFu, p1, 2);
                if ((lane & 3) == 0) {
                    int r0 = m0 + (lane >> 2);
                    P[((branch << 7) + r0) * 4 + (wid & 3)] = p0;
                    P[((branch << 7) + r0 + 8) * 4 + (wid & 3)] = p1;
                }
            }
        }
        __syncthreads();

        // ===== final reduce + store =====
        {
            int br = tid >> 7, m = tid & 127;
            float4 pv = *(const float4*)(smem + SM_P + ((br << 7) + m) * 16);
            float b4 = *(const float*)(smem + SM_B4 + br * 4);
            out[br * NEDGES + t * TILE_M + m] = pv.x + pv.y + pv.z + pv.w + b4;
        }
        // no hazard: next phase that writes P is 3 syncs away; gather writes X,
        // whose last readers (L3 ldmatrix) completed before the sync above.
    }
}

extern "C" void kernel_launch(void* const* d_in, const int* in_sizes, int n_in,
                              void* d_out, int out_size) {
    const float* x_src = (const float*)d_in[0];
    const float* x_dst = (const float*)d_in[1];
    const int* eidx = (const int*)d_in[2];
    const float* ew1 = (const float*)d_in[3];
    const float* eb1 = (const float*)d_in[4];
    const float* ww1 = (const float*)d_in[5];
    const float* wb1 = (const float*)d_in[6];
    const float* ew2 = (const float*)d_in[7];
    const float* eb2 = (const float*)d_in[8];
    const float* ww2 = (const float*)d_in[9];
    const float* wb2 = (const float*)d_in[10];
    const float* ew3 = (const float*)d_in[11];
    const float* eb3 = (const float*)d_in[12];
    const float* ww3 = (const float*)d_in[13];
    const float* wb3 = (const float*)d_in[14];
    const float* ew4 = (const float*)d_in[15];
    const float* eb4 = (const float*)d_in[16];
    const float* ww4 = (const float*)d_in[17];
    const float* wb4 = (const float*)d_in[18];
    float* out = (float*)d_out;

    int nsm = 148;
    cudaDeviceGetAttribute(&nsm, cudaDevAttrMultiProcessorCount, 0);

    cudaFuncSetAttribute(regressor_mma_kernel,
                         cudaFuncAttributeMaxDynamicSharedMemorySize, SMEM_BYTES);

    regressor_mma_kernel<<<nsm, TPB, SMEM_BYTES>>>(
        x_src, x_dst, eidx, ew1, eb1, ww1, wb1, ew2, eb2, ww2, wb2,
        ew3, eb3, ww3, wb3, ew4, eb4, ww4, wb4, out);
}

// round 6
// speedup vs baseline: 3.6162x; 1.0671x over previous
#include <cuda_runtime.h>
#include <cuda_bf16.h>
#include <cstdint>

#define NEDGES 2000000
#define TILE_M 128
#define NTILES (NEDGES / TILE_M)
#define TPB 512

// activation buffers: [128 rows][136 bf16] (272 B stride, conflict-free ldmatrix)
#define ROWB 272
#define SM_XH 0
#define SM_XL 34816
#define SM_YH 69632
#define SM_YL 104448
#define SM_P  139264            // float[2][128][4]
#define SM_B4 143360            // float[2]
#define SMEM_BYTES 143424

__device__ __forceinline__ uint32_t smem_u32(const void* p) {
    uint32_t a;
    asm("{ .reg .u64 t; cvta.to.shared.u64 t, %1; cvt.u32.u64 %0, t; }" : "=r"(a) : "l"(p));
    return a;
}
__device__ __forceinline__ float lrelu(float z) { return fmaxf(z, 0.01f * z); }

// pack 2 f32 -> bf16x2 (a in low half)
__device__ __forceinline__ uint32_t pk2(float a, float b) {
    uint32_t r;
    asm("cvt.rn.bf16x2.f32 %0, %1, %2;" : "=r"(r) : "f"(b), "f"(a));
    return r;
}
// split f32 pair -> hi bf16x2 + lo bf16x2
__device__ __forceinline__ void split2(float a, float b, uint32_t& hp, uint32_t& lp) {
    hp = pk2(a, b);
    float ha = __uint_as_float(hp << 16);
    float hb = __uint_as_float(hp & 0xFFFF0000u);
    lp = pk2(a - ha, b - hb);
}

__device__ __forceinline__ void ldsm4(uint32_t addr, uint32_t& a0, uint32_t& a1,
                                      uint32_t& a2, uint32_t& a3) {
    asm volatile("ldmatrix.sync.aligned.m8n8.x4.shared.b16 {%0,%1,%2,%3}, [%4];"
                 : "=r"(a0), "=r"(a1), "=r"(a2), "=r"(a3) : "r"(addr));
}
__device__ __forceinline__ void mma16816(float* d, uint32_t a0, uint32_t a1,
                                         uint32_t a2, uint32_t a3,
                                         uint32_t b0, uint32_t b1) {
    asm volatile(
        "mma.sync.aligned.m16n8k16.row.col.f32.bf16.bf16.f32 "
        "{%0,%1,%2,%3}, {%4,%5,%6,%7}, {%8,%9}, {%0,%1,%2,%3};"
        : "+f"(d[0]), "+f"(d[1]), "+f"(d[2]), "+f"(d[3])
        : "r"(a0), "r"(a1), "r"(a2), "r"(a3), "r"(b0), "r"(b1));
}

// build one 8x8 B fragment (col-major k8 x n8) from global W[k][n] (row-major, ldn)
__device__ __forceinline__ void make_bfrag(const float* __restrict__ W, int ldn,
                                           int k0, int n0, int lane,
                                           uint32_t& h, uint32_t& l) {
    int g = lane >> 2, tg = lane & 3;
    const float* p = W + (size_t)(k0 + tg * 2) * ldn + (n0 + g);
    float wa = p[0], wb = p[ldn];
    h = pk2(wa, wb);
    float ha = __uint_as_float(h << 16);
    float hb = __uint_as_float(h & 0xFFFF0000u);
    l = pk2(wa - ha, wb - hb);
}

__global__ void __launch_bounds__(TPB, 1)
regressor_mma_kernel(const float* __restrict__ x_src,
                     const float* __restrict__ x_dst,
                     const int* __restrict__ eidx,
                     const float* __restrict__ ew1, const float* __restrict__ eb1,
                     const float* __restrict__ ww1, const float* __restrict__ wb1,
                     const float* __restrict__ ew2, const float* __restrict__ eb2,
                     const float* __restrict__ ww2, const float* __restrict__ wb2,
                     const float* __restrict__ ew3, const float* __restrict__ eb3,
                     const float* __restrict__ ww3, const float* __restrict__ wb3,
                     const float* __restrict__ ew4, const float* __restrict__ eb4,
                     const float* __restrict__ ww4, const float* __restrict__ wb4,
                     float* __restrict__ out) {
    extern __shared__ char smem[];
    const uint32_t smb = smem_u32(smem);
    const int tid = threadIdx.x;
    const int wid = tid >> 5, lane = tid & 31;
    const int branch = wid >> 3;           // 0 = exists, 1 = weight
    const int w8 = wid & 7;                // warp within branch
    const int nw = w8 * 8;                 // 8-col n-slice for L1/L2
    const int mg = w8 >> 2;                // L3 m-group (0: mt 0-3, 1: mt 4-7)
    const int n3 = (w8 & 3) * 8;           // L3 n-slice

    // ---------- per-warp weight fragments (registers, built once) ----------
    const float* W1 = branch ? ww1 : ew1;  // [128][64]
    const float* W2 = branch ? ww2 : ew2;  // [64][64]
    const float* W3 = branch ? ww3 : ew3;  // [64][32]
    const float* B1 = branch ? wb1 : eb1;
    const float* B2 = branch ? wb2 : eb2;
    const float* B3 = branch ? wb3 : eb3;
    const float* W4 = branch ? ww4 : ew4;

    uint32_t B1h[8][2], B1l[8][2];
#pragma unroll
    for (int kt = 0; kt < 8; kt++)
#pragma unroll
        for (int r = 0; r < 2; r++)
            make_bfrag(W1, 64, kt * 16 + r * 8, nw, lane, B1h[kt][r], B1l[kt][r]);

    uint32_t B2h[4][2], B2l[4][2];
#pragma unroll
    for (int kt = 0; kt < 4; kt++)
#pragma unroll
        for (int r = 0; r < 2; r++)
            make_bfrag(W2, 64, kt * 16 + r * 8, nw, lane, B2h[kt][r], B2l[kt][r]);

    uint32_t B3h[4][2], B3l[4][2];
#pragma unroll
    for (int kt = 0; kt < 4; kt++)
#pragma unroll
        for (int r = 0; r < 2; r++)
            make_bfrag(W3, 32, kt * 16 + r * 8, n3, lane, B3h[kt][r], B3l[kt][r]);

    // per-thread biases for the columns this thread's c-frag covers
    float b1v[2], b2v[2], b3v[2], w4v[2];
#pragma unroll
    for (int j = 0; j < 2; j++) {
        int c = nw + (lane & 3) * 2 + j;
        b1v[j] = B1[c];
        b2v[j] = B2[c];
        int c3 = n3 + (lane & 3) * 2 + j;
        b3v[j] = B3[c3];
        w4v[j] = W4[c3];
    }
    if (tid == 0) {
        *(float*)(smem + SM_B4 + 0) = eb4[0];
        *(float*)(smem + SM_B4 + 4) = wb4[0];
    }
    __syncthreads();

    const uint32_t xh = smb + SM_XH, xl = smb + SM_XL;
    const uint32_t yh = smb + SM_YH, yl = smb + SM_YL;

    for (int t = blockIdx.x; t < NTILES; t += gridDim.x) {
        // ===== gather: warp w owns edges [8w, 8w+8); lanes 0-15 src, 16-31 dst =====
        {
            const int half = lane >> 4;
            const int c16 = lane & 15;
#pragma unroll 2
            for (int i = 0; i < 8; i++) {
                int m = wid * 8 + i;
                int e = t * TILE_M + m;
                int idx = half ? eidx[NEDGES + e] : eidx[e];
                const float* row = (half ? x_dst : x_src) + (size_t)idx * 64;
                float4 v = ((const float4*)row)[c16];
                uint32_t h0, l0, h1, l1;
                split2(v.x, v.y, h0, l0);
                split2(v.z, v.w, h1, l1);
                uint32_t off = (uint32_t)m * ROWB + half * 128u + c16 * 8u;
                *(uint2*)(smem + SM_XH + off) = make_uint2(h0, h1);
                *(uint2*)(smem + SM_XL + off) = make_uint2(l0, l1);
            }
        }
        __syncthreads();

        // ===== L1: X[128x128] -> Y[128x128], 8-col slice per warp =====
        {
            const int colout = branch * 64 + nw;
#pragma unroll 1
            for (int mt = 0; mt < 8; mt++) {
                int m0 = mt * 16;
                float aP[4] = {}, aQ1[4] = {}, aQ2[4] = {};
                uint32_t arow = (uint32_t)(m0 + (lane & 15)) * ROWB + (lane >> 4) * 16u;
#pragma unroll
                for (int kt = 0; kt < 8; kt++) {
                    uint32_t h0, h1, h2, h3, l0, l1, l2, l3;
                    ldsm4(xh + arow + kt * 32u, h0, h1, h2, h3);
                    ldsm4(xl + arow + kt * 32u, l0, l1, l2, l3);
                    mma16816(aP, h0, h1, h2, h3, B1h[kt][0], B1h[kt][1]);
                    mma16816(aQ1, h0, h1, h2, h3, B1l[kt][0], B1l[kt][1]);
                    mma16816(aQ2, l0, l1, l2, l3, B1h[kt][0], B1h[kt][1]);
                }
                float v0 = lrelu(aP[0] + aQ1[0] + aQ2[0] + b1v[0]);
                float v1 = lrelu(aP[1] + aQ1[1] + aQ2[1] + b1v[1]);
                float v2 = lrelu(aP[2] + aQ1[2] + aQ2[2] + b1v[0]);
                float v3 = lrelu(aP[3] + aQ1[3] + aQ2[3] + b1v[1]);
                uint32_t hp0, lp0, hp1, lp1;
                split2(v0, v1, hp0, lp0);
                split2(v2, v3, hp1, lp1);
                uint32_t col2 = (uint32_t)(colout + (lane & 3) * 2) * 2u;
                uint32_t o0 = (uint32_t)(m0 + (lane >> 2)) * ROWB + col2;
                uint32_t o1 = (uint32_t)(m0 + 8 + (lane >> 2)) * ROWB + col2;
                *(uint32_t*)(smem + SM_YH + o0) = hp0;
                *(uint32_t*)(smem + SM_YL + o0) = lp0;
                *(uint32_t*)(smem + SM_YH + o1) = hp1;
                *(uint32_t*)(smem + SM_YL + o1) = lp1;
            }
        }
        __syncthreads();

        // ===== L2: Y (cols branch*64..+63) -> X, 8-col slice per warp =====
        {
            const int colout = branch * 64 + nw;
            const uint32_t abase = (uint32_t)branch * 128u;
#pragma unroll 1
            for (int mt = 0; mt < 8; mt++) {
                int m0 = mt * 16;
                float aP[4] = {}, aQ1[4] = {}, aQ2[4] = {};
                uint32_t arow = (uint32_t)(m0 + (lane & 15)) * ROWB + abase + (lane >> 4) * 16u;
#pragma unroll
                for (int kt = 0; kt < 4; kt++) {
                    uint32_t h0, h1, h2, h3, l0, l1, l2, l3;
                    ldsm4(yh + arow + kt * 32u, h0, h1, h2, h3);
                    ldsm4(yl + arow + kt * 32u, l0, l1, l2, l3);
                    mma16816(aP, h0, h1, h2, h3, B2h[kt][0], B2h[kt][1]);
                    mma16816(aQ1, h0, h1, h2, h3, B2l[kt][0], B2l[kt][1]);
                    mma16816(aQ2, l0, l1, l2, l3, B2h[kt][0], B2h[kt][1]);
                }
                float v0 = lrelu(aP[0] + aQ1[0] + aQ2[0] + b2v[0]);
                float v1 = lrelu(aP[1] + aQ1[1] + aQ2[1] + b2v[1]);
                float v2 = lrelu(aP[2] + aQ1[2] + aQ2[2] + b2v[0]);
                float v3 = lrelu(aP[3] + aQ1[3] + aQ2[3] + b2v[1]);
                uint32_t hp0, lp0, hp1, lp1;
                split2(v0, v1, hp0, lp0);
                split2(v2, v3, hp1, lp1);
                uint32_t col2 = (uint32_t)(colout + (lane & 3) * 2) * 2u;
                uint32_t o0 = (uint32_t)(m0 + (lane >> 2)) * ROWB + col2;
                uint32_t o1 = (uint32_t)(m0 + 8 + (lane >> 2)) * ROWB + col2;
                *(uint32_t*)(smem + SM_XH + o0) = hp0;
                *(uint32_t*)(smem + SM_XL + o0) = lp0;
                *(uint32_t*)(smem + SM_XH + o1) = hp1;
                *(uint32_t*)(smem + SM_XL + o1) = lp1;
            }
        }
        __syncthreads();

        // ===== L3 + L4: X (cols branch*64..) -> partials in P =====
        {
            const uint32_t abase = (uint32_t)branch * 128u;
            float* P = (float*)(smem + SM_P);
#pragma unroll 1
            for (int i = 0; i < 4; i++) {
                int mt = mg * 4 + i;
                int m0 = mt * 16;
                float aP[4] = {}, aQ1[4] = {}, aQ2[4] = {};
                uint32_t arow = (uint32_t)(m0 + (lane & 15)) * ROWB + abase + (lane >> 4) * 16u;
#pragma unroll
                for (int kt = 0; kt < 4; kt++) {
                    uint32_t h0, h1, h2, h3, l0, l1, l2, l3;
                    ldsm4(xh + arow + kt * 32u, h0, h1, h2, h3);
                    ldsm4(xl + arow + kt * 32u, l0, l1, l2, l3);
                    mma16816(aP, h0, h1, h2, h3, B3h[kt][0], B3h[kt][1]);
                    mma16816(aQ1, h0, h1, h2, h3, B3l[kt][0], B3l[kt][1]);
                    mma16816(aQ2, l0, l1, l2, l3, B3h[kt][0], B3h[kt][1]);
                }
                float p0 = lrelu(aP[0] + aQ1[0] + aQ2[0] + b3v[0]) * w4v[0] +
                           lrelu(aP[1] + aQ1[1] + aQ2[1] + b3v[1]) * w4v[1];
                float p1 = lrelu(aP[2] + aQ1[2] + aQ2[2] + b3v[0]) * w4v[0] +
                           lrelu(aP[3] + aQ1[3] + aQ2[3] + b3v[1]) * w4v[1];
                p0 += __shfl_xor_sync(0xFFFFFFFFu, p0, 1);
                p0 += __shfl_xor_sync(0xFFFFFFFFu, p0, 2);
                p1 += __shfl_xor_sync(0xFFFFFFFFu, p1, 1);
                p1 += __shfl_xor_sync(0xFFFFFFFFu, p1, 2);
                if ((lane & 3) == 0) {
                    int r0 = m0 + (lane >> 2);
                    P[((branch << 7) + r0) * 4 + (w8 & 3)] = p0;
                    P[((branch << 7) + r0 + 8) * 4 + (w8 & 3)] = p1;
                }
            }
        }
        __syncthreads();

        // ===== final reduce + store (256 threads) =====
        if (tid < 256) {
            int br = tid >> 7, m = tid & 127;
            float4 pv = *(const float4*)(smem + SM_P + ((br << 7) + m) * 16);
            float b4 = *(const float*)(smem + SM_B4 + br * 4);
            out[br * NEDGES + t * TILE_M + m] = pv.x + pv.y + pv.z + pv.w + b4;
        }
        // no hazard: gather (next writer of X) happens after this iteration's
        // trailing __syncthreads at loop top; L3 ldmatrix (last X reader) done
        // before the sync above. P is re-written only after 3 more syncs.
    }
}

extern "C" void kernel_launch(void* const* d_in, const int* in_sizes, int n_in,
                              void* d_out, int out_size) {
    const float* x_src = (const float*)d_in[0];
    const float* x_dst = (const float*)d_in[1];
    const int* eidx = (const int*)d_in[2];
    const float* ew1 = (const float*)d_in[3];
    const float* eb1 = (const float*)d_in[4];
    const float* ww1 = (const float*)d_in[5];
    const float* wb1 = (const float*)d_in[6];
    const float* ew2 = (const float*)d_in[7];
    const float* eb2 = (const float*)d_in[8];
    const float* ww2 = (const float*)d_in[9];
    const float* wb2 = (const float*)d_in[10];
    const float* ew3 = (const float*)d_in[11];
    const float* eb3 = (const float*)d_in[12];
    const float* ww3 = (const float*)d_in[13];
    const float* wb3 = (const float*)d_in[14];
    const float* ew4 = (const float*)d_in[15];
    const float* eb4 = (const float*)d_in[16];
    const float* ww4 = (const float*)d_in[17];
    const float* wb4 = (const float*)d_in[18];
    float* out = (float*)d_out;

    int nsm = 148;
    cudaDeviceGetAttribute(&nsm, cudaDevAttrMultiProcessorCount, 0);

    cudaFuncSetAttribute(regressor_mma_kernel,
                         cudaFuncAttributeMaxDynamicSharedMemorySize, SMEM_BYTES);

    regressor_mma_kernel<<<nsm, TPB, SMEM_BYTES>>>(
        x_src, x_dst, eidx, ew1, eb1, ww1, wb1, ew2, eb2, ww2, wb2,
        ew3, eb3, ww3, wb3, ew4, eb4, ww4, wb4, out);
}

// round 7
// speedup vs baseline: 5.7222x; 1.5824x over previous
#include <cuda_runtime.h>
#include <cuda_fp16.h>
#include <cstdint>

#define NEDGES 2000000
#define TILE_M 128
#define NTILES (NEDGES / TILE_M)
#define TPB 512

// activation buffers: [128 rows][136 fp16] (272 B stride, conflict-free ldmatrix)
#define ROWB 272
#define SM_XH 0
#define SM_YH 34816
#define SM_P  69632             // float[2][128][4]
#define SM_B4 73728             // float[2]
#define SMEM_BYTES 73792

#define LO_SCALE 2048.0f        // 2^11: keep B-lo in fp16 normal range
#define LO_INV   (1.0f / 2048.0f)

__device__ __forceinline__ uint32_t smem_u32(const void* p) {
    uint32_t a;
    asm("{ .reg .u64 t; cvta.to.shared.u64 t, %1; cvt.u32.u64 %0, t; }" : "=r"(a) : "l"(p));
    return a;
}
__device__ __forceinline__ float lrelu(float z) { return fmaxf(z, 0.01f * z); }

// pack 2 f32 -> fp16x2 (a in low half)
__device__ __forceinline__ uint32_t pkh2(float a, float b) {
    __half2 h = __floats2half2_rn(a, b);
    return *(uint32_t*)&h;
}

__device__ __forceinline__ void ldsm4(uint32_t addr, uint32_t& a0, uint32_t& a1,
                                      uint32_t& a2, uint32_t& a3) {
    asm volatile("ldmatrix.sync.aligned.m8n8.x4.shared.b16 {%0,%1,%2,%3}, [%4];"
                 : "=r"(a0), "=r"(a1), "=r"(a2), "=r"(a3) : "r"(addr));
}
__device__ __forceinline__ void mma16816(float* d, uint32_t a0, uint32_t a1,
                                         uint32_t a2, uint32_t a3,
                                         uint32_t b0, uint32_t b1) {
    asm volatile(
        "mma.sync.aligned.m16n8k16.row.col.f32.f16.f16.f32 "
        "{%0,%1,%2,%3}, {%4,%5,%6,%7}, {%8,%9}, {%0,%1,%2,%3};"
        : "+f"(d[0]), "+f"(d[1]), "+f"(d[2]), "+f"(d[3])
        : "r"(a0), "r"(a1), "r"(a2), "r"(a3), "r"(b0), "r"(b1));
}

// 8x8 B fragment (col-major k8 x n8) from global W[k][n]: fp16 hi + scaled fp16 lo
__device__ __forceinline__ void make_hfrag(const float* __restrict__ W, int ldn,
                                           int k0, int n0, int lane,
                                           uint32_t& h, uint32_t& l) {
    int g = lane >> 2, tg = lane & 3;
    const float* p = W + (size_t)(k0 + tg * 2) * ldn + (n0 + g);
    float wa = p[0], wb = p[ldn];
    h = pkh2(wa, wb);
    __half2 hh = *(__half2*)&h;
    float ra = (wa - __low2float(hh)) * LO_SCALE;
    float rb = (wb - __high2float(hh)) * LO_SCALE;
    l = pkh2(ra, rb);
}

__global__ void __launch_bounds__(TPB, 1)
regressor_mma_kernel(const float* __restrict__ x_src,
                     const float* __restrict__ x_dst,
                     const int* __restrict__ eidx,
                     const float* __restrict__ ew1, const float* __restrict__ eb1,
                     const float* __restrict__ ww1, const float* __restrict__ wb1,
                     const float* __restrict__ ew2, const float* __restrict__ eb2,
                     const float* __restrict__ ww2, const float* __restrict__ wb2,
                     const float* __restrict__ ew3, const float* __restrict__ eb3,
                     const float* __restrict__ ww3, const float* __restrict__ wb3,
                     const float* __restrict__ ew4, const float* __restrict__ eb4,
                     const float* __restrict__ ww4, const float* __restrict__ wb4,
                     float* __restrict__ out) {
    extern __shared__ char smem[];
    const uint32_t smb = smem_u32(smem);
    const int tid = threadIdx.x;
    const int wid = tid >> 5, lane = tid & 31;
    const int branch = wid >> 3;           // 0 = exists, 1 = weight
    const int w8 = wid & 7;                // warp within branch
    const int nw = w8 * 8;                 // 8-col n-slice for L1/L2
    const int mg = w8 >> 2;                // L3 m-group (0: mt 0-3, 1: mt 4-7)
    const int n3 = (w8 & 3) * 8;           // L3 n-slice

    // ---------- per-warp weight fragments (registers, built once) ----------
    const float* W1 = branch ? ww1 : ew1;  // [128][64]
    const float* W2 = branch ? ww2 : ew2;  // [64][64]
    const float* W3 = branch ? ww3 : ew3;  // [64][32]
    const float* B1 = branch ? wb1 : eb1;
    const float* B2 = branch ? wb2 : eb2;
    const float* B3 = branch ? wb3 : eb3;
    const float* W4 = branch ? ww4 : ew4;

    uint32_t B1h[8][2], B1l[8][2];
#pragma unroll
    for (int kt = 0; kt < 8; kt++)
#pragma unroll
        for (int r = 0; r < 2; r++)
            make_hfrag(W1, 64, kt * 16 + r * 8, nw, lane, B1h[kt][r], B1l[kt][r]);

    uint32_t B2h[4][2], B2l[4][2];
#pragma unroll
    for (int kt = 0; kt < 4; kt++)
#pragma unroll
        for (int r = 0; r < 2; r++)
            make_hfrag(W2, 64, kt * 16 + r * 8, nw, lane, B2h[kt][r], B2l[kt][r]);

    uint32_t B3h[4][2], B3l[4][2];
#pragma unroll
    for (int kt = 0; kt < 4; kt++)
#pragma unroll
        for (int r = 0; r < 2; r++)
            make_hfrag(W3, 32, kt * 16 + r * 8, n3, lane, B3h[kt][r], B3l[kt][r]);

    // per-thread biases for the columns this thread's c-frag covers
    float b1v[2], b2v[2], b3v[2], w4v[2];
#pragma unroll
    for (int j = 0; j < 2; j++) {
        int c = nw + (lane & 3) * 2 + j;
        b1v[j] = B1[c];
        b2v[j] = B2[c];
        int c3 = n3 + (lane & 3) * 2 + j;
        b3v[j] = B3[c3];
        w4v[j] = W4[c3];
    }
    if (tid == 0) {
        *(float*)(smem + SM_B4 + 0) = eb4[0];
        *(float*)(smem + SM_B4 + 4) = wb4[0];
    }
    __syncthreads();

    const uint32_t xh = smb + SM_XH;
    const uint32_t yh = smb + SM_YH;

    for (int t = blockIdx.x; t < NTILES; t += gridDim.x) {
        // ===== gather: warp w owns edges [8w, 8w+8); lanes 0-15 src, 16-31 dst =====
        {
            const int half = lane >> 4;
            const int c16 = lane & 15;
#pragma unroll 2
            for (int i = 0; i < 8; i++) {
                int m = wid * 8 + i;
                int e = t * TILE_M + m;
                int idx = half ? eidx[NEDGES + e] : eidx[e];
                const float* row = (half ? x_dst : x_src) + (size_t)idx * 64;
                float4 v = ((const float4*)row)[c16];
                uint32_t h0 = pkh2(v.x, v.y);
                uint32_t h1 = pkh2(v.z, v.w);
                uint32_t off = (uint32_t)m * ROWB + half * 128u + c16 * 8u;
                *(uint2*)(smem + SM_XH + off) = make_uint2(h0, h1);
            }
        }
        __syncthreads();

        // ===== L1: X[128x128] -> Y[128x128], 8-col slice per warp =====
        {
            const int colout = branch * 64 + nw;
#pragma unroll 1
            for (int mt = 0; mt < 8; mt++) {
                int m0 = mt * 16;
                float aP[4] = {}, aQ[4] = {};
                uint32_t arow = (uint32_t)(m0 + (lane & 15)) * ROWB + (lane >> 4) * 16u;
#pragma unroll
                for (int kt = 0; kt < 8; kt++) {
                    uint32_t h0, h1, h2, h3;
                    ldsm4(xh + arow + kt * 32u, h0, h1, h2, h3);
                    mma16816(aP, h0, h1, h2, h3, B1h[kt][0], B1h[kt][1]);
                    mma16816(aQ, h0, h1, h2, h3, B1l[kt][0], B1l[kt][1]);
                }
                float v0 = lrelu(fmaf(aQ[0], LO_INV, aP[0]) + b1v[0]);
                float v1 = lrelu(fmaf(aQ[1], LO_INV, aP[1]) + b1v[1]);
                float v2 = lrelu(fmaf(aQ[2], LO_INV, aP[2]) + b1v[0]);
                float v3 = lrelu(fmaf(aQ[3], LO_INV, aP[3]) + b1v[1]);
                uint32_t col2 = (uint32_t)(colout + (lane & 3) * 2) * 2u;
                uint32_t o0 = (uint32_t)(m0 + (lane >> 2)) * ROWB + col2;
                uint32_t o1 = (uint32_t)(m0 + 8 + (lane >> 2)) * ROWB + col2;
                *(uint32_t*)(smem + SM_YH + o0) = pkh2(v0, v1);
                *(uint32_t*)(smem + SM_YH + o1) = pkh2(v2, v3);
            }
        }
        __syncthreads();

        // ===== L2: Y (cols branch*64..+63) -> X, 8-col slice per warp =====
        {
            const int colout = branch * 64 + nw;
            const uint32_t abase = (uint32_t)branch * 128u;
#pragma unroll 1
            for (int mt = 0; mt < 8; mt++) {
                int m0 = mt * 16;
                float aP[4] = {}, aQ[4] = {};
                uint32_t arow = (uint32_t)(m0 + (lane & 15)) * ROWB + abase + (lane >> 4) * 16u;
#pragma unroll
                for (int kt = 0; kt < 4; kt++) {
                    uint32_t h0, h1, h2, h3;
                    ldsm4(yh + arow + kt * 32u, h0, h1, h2, h3);
                    mma16816(aP, h0, h1, h2, h3, B2h[kt][0], B2h[kt][1]);
                    mma16816(aQ, h0, h1, h2, h3, B2l[kt][0], B2l[kt][1]);
                }
                float v0 = lrelu(fmaf(aQ[0], LO_INV, aP[0]) + b2v[0]);
                float v1 = lrelu(fmaf(aQ[1], LO_INV, aP[1]) + b2v[1]);
                float v2 = lrelu(fmaf(aQ[2], LO_INV, aP[2]) + b2v[0]);
                float v3 = lrelu(fmaf(aQ[3], LO_INV, aP[3]) + b2v[1]);
                uint32_t col2 = (uint32_t)(colout + (lane & 3) * 2) * 2u;
                uint32_t o0 = (uint32_t)(m0 + (lane >> 2)) * ROWB + col2;
                uint32_t o1 = (uint32_t)(m0 + 8 + (lane >> 2)) * ROWB + col2;
                *(uint32_t*)(smem + SM_XH + o0) = pkh2(v0, v1);
                *(uint32_t*)(smem + SM_XH + o1) = pkh2(v2, v3);
            }
        }
        __syncthreads();

        // ===== L3 + L4: X (cols branch*64..) -> partials in P =====
        {
            const uint32_t abase = (uint32_t)branch * 128u;
            float* P = (float*)(smem + SM_P);
#pragma unroll 1
            for (int i = 0; i < 4; i++) {
                int mt = mg * 4 + i;
                int m0 = mt * 16;
                float aP[4] = {}, aQ[4] = {};
                uint32_t arow = (uint32_t)(m0 + (lane & 15)) * ROWB + abase + (lane >> 4) * 16u;
#pragma unroll
                for (int kt = 0; kt < 4; kt++) {
                    uint32_t h0, h1, h2, h3;
                    ldsm4(xh + arow + kt * 32u, h0, h1, h2, h3);
                    mma16816(aP, h0, h1, h2, h3, B3h[kt][0], B3h[kt][1]);
                    mma16816(aQ, h0, h1, h2, h3, B3l[kt][0], B3l[kt][1]);
                }
                float p0 = lrelu(fmaf(aQ[0], LO_INV, aP[0]) + b3v[0]) * w4v[0] +
                           lrelu(fmaf(aQ[1], LO_INV, aP[1]) + b3v[1]) * w4v[1];
                float p1 = lrelu(fmaf(aQ[2], LO_INV, aP[2]) + b3v[0]) * w4v[0] +
                           lrelu(fmaf(aQ[3], LO_INV, aP[3]) + b3v[1]) * w4v[1];
                p0 += __shfl_xor_sync(0xFFFFFFFFu, p0, 1);
                p0 += __shfl_xor_sync(0xFFFFFFFFu, p0, 2);
                p1 += __shfl_xor_sync(0xFFFFFFFFu, p1, 1);
                p1 += __shfl_xor_sync(0xFFFFFFFFu, p1, 2);
                if ((lane & 3) == 0) {
                    int r0 = m0 + (lane >> 2);
                    P[((branch << 7) + r0) * 4 + (w8 & 3)] = p0;
                    P[((branch << 7) + r0 + 8) * 4 + (w8 & 3)] = p1;
                }
            }
        }
        __syncthreads();

        // ===== final reduce + store (256 threads) =====
        if (tid < 256) {
            int br = tid >> 7, m = tid & 127;
            float4 pv = *(const float4*)(smem + SM_P + ((br << 7) + m) * 16);
            float b4 = *(const float*)(smem + SM_B4 + br * 4);
            out[br * NEDGES + t * TILE_M + m] = pv.x + pv.y + pv.z + pv.w + b4;
        }
        // hazards: gather (next X writer) is after the loop-top sync; L3
        // ldmatrix (last X reader) completed before the sync above; P is
        // rewritten only after 3 more syncs.
    }
}

extern "C" void kernel_launch(void* const* d_in, const int* in_sizes, int n_in,
                              void* d_out, int out_size) {
    const float* x_src = (const float*)d_in[0];
    const float* x_dst = (const float*)d_in[1];
    const int* eidx = (const int*)d_in[2];
    const float* ew1 = (const float*)d_in[3];
    const float* eb1 = (const float*)d_in[4];
    const float* ww1 = (const float*)d_in[5];
    const float* wb1 = (const float*)d_in[6];
    const float* ew2 = (const float*)d_in[7];
    const float* eb2 = (const float*)d_in[8];
    const float* ww2 = (const float*)d_in[9];
    const float* wb2 = (const float*)d_in[10];
    const float* ew3 = (const float*)d_in[11];
    const float* eb3 = (const float*)d_in[12];
    const float* ww3 = (const float*)d_in[13];
    const float* wb3 = (const float*)d_in[14];
    const float* ew4 = (const float*)d_in[15];
    const float* eb4 = (const float*)d_in[16];
    const float* ww4 = (const float*)d_in[17];
    const float* wb4 = (const float*)d_in[18];
    float* out = (float*)d_out;

    int nsm = 148;
    cudaDeviceGetAttribute(&nsm, cudaDevAttrMultiProcessorCount, 0);

    cudaFuncSetAttribute(regressor_mma_kernel,
                         cudaFuncAttributeMaxDynamicSharedMemorySize, SMEM_BYTES);

    regressor_mma_kernel<<<nsm, TPB, SMEM_BYTES>>>(
        x_src, x_dst, eidx, ew1, eb1, ww1, wb1, ew2, eb2, ww2, wb2,
        ew3, eb3, ww3, wb3, ew4, eb4, ww4, wb4, out);
}